// round 17
// baseline (speedup 1.0000x reference)
#include <cuda_runtime.h>
#include <cuda_bf16.h>
#include <cstdint>

// KAN layer as tensor-core GEMM, SINGLE kernel, full-K per block.
//   out[1024,128] = A[1024,1024] @ B^T + bias
//   A[n, j*8+k] = Catmull-Rom basis (built per chunk, bf16 hi/lo split)
//   B[o, j*8+k] = weights[o,j]*coeffs[o,j,k] (built per chunk, bf16 hi/lo)
// 3-pass bf16 mma (hh + hl + lh), fp32 accumulators ~ fp32 accuracy.
//
// Grid (32 mt x 4 oh) = 128 blocks, 256 threads. Block tile: 32m x 32o x K=1024,
// looped over 4 k-chunks of 256 k with DOUBLE-BUFFERED smem (build(c+1) is
// interleaved with MMA(c); one __syncthreads per chunk).
// 8 warps = 2 m16-slices x 4 n8-slices; warp tile m16 x n8 x k1024.
// No k-split across blocks => no reduce kernel, no partials: out written direct.

#define D_IN  128
#define D_OUT 128
#define KNOTS 8
#define N_ROWS 1024
#define MT 32                 // m rows per block
#define OB 32                 // o cols per block
#define NCH 4                 // k-chunks
#define CJ 32                 // j per chunk (= 256 k)

#define RSB 528               // SMEM row stride bytes (512 data + 16 pad)
#define SEG (MT * RSB)        // 16896 bytes per sub-tile
#define BUF (4 * SEG)         // Ahi, Alo, Bhi, Blo
#define SM_TOTAL (2 * BUF)    // 135168

__device__ __forceinline__ uint32_t smem_u32(const void* p) {
    uint32_t a;
    asm("{ .reg .u64 t; cvta.to.shared.u64 t, %1; cvt.u32.u64 %0, t; }" : "=r"(a) : "l"(p));
    return a;
}

#define LDSM4(r0, r1, r2, r3, addr) \
    asm volatile("ldmatrix.sync.aligned.m8n8.x4.shared.b16 {%0,%1,%2,%3}, [%4];" \
        : "=r"(r0), "=r"(r1), "=r"(r2), "=r"(r3) : "r"(addr))

#define MMA16816(c, a0, a1, a2, a3, b0, b1) \
    asm volatile("mma.sync.aligned.m16n8k16.row.col.f32.bf16.bf16.f32 " \
        "{%0,%1,%2,%3}, {%4,%5,%6,%7}, {%8,%9}, {%0,%1,%2,%3};" \
        : "+f"((c)[0]), "+f"((c)[1]), "+f"((c)[2]), "+f"((c)[3]) \
        : "r"(a0), "r"(a1), "r"(a2), "r"(a3), "r"(b0), "r"(b1))

// Split 8 fp32 -> bf16 hi/lo pairs and store 16B each to smem.
__device__ __forceinline__ void split_store(char* smem, int off_hi, int off_lo,
                                            const float* v) {
    __nv_bfloat162 hi[4], lo[4];
    #pragma unroll
    for (int p = 0; p < 4; p++) {
        __nv_bfloat16 h0 = __float2bfloat16(v[2 * p]);
        __nv_bfloat16 h1 = __float2bfloat16(v[2 * p + 1]);
        hi[p] = __nv_bfloat162(h0, h1);
        lo[p] = __nv_bfloat162(
            __float2bfloat16(v[2 * p]     - __bfloat162float(h0)),
            __float2bfloat16(v[2 * p + 1] - __bfloat162float(h1)));
    }
    *(uint4*)(smem + off_hi) = *(uint4*)hi;
    *(uint4*)(smem + off_lo) = *(uint4*)lo;
}

__global__ __launch_bounds__(256, 1) void kan_mma_kernel(
    const float* __restrict__ x,
    const float* __restrict__ coeffs,
    const float* __restrict__ weights,
    const float* __restrict__ bias,
    float* __restrict__ out) {
    extern __shared__ __align__(16) char smem[];
    const uint32_t sb = smem_u32(smem);
    const int tid  = threadIdx.x;
    const int wid  = tid >> 5;
    const int lane = tid & 31;
    const int wm   = wid & 1;        // m16 slice (0/1)
    const int wn   = wid >> 1;       // n8 slice (0..3)
    const int mt   = blockIdx.x;     // 32-row m-tile
    const int oh   = blockIdx.y;     // 32-col o-tile

    // ---- chunk builder: A (32m x 32j) + B (32o x 32j) into buffer b ----
    auto build = [&](int c, int b) {
        char* base = smem + b * BUF;
        // A: 1024 evals, 4 per thread
        #pragma unroll
        for (int e = tid; e < MT * CJ; e += 256) {
            int m  = e >> 5;
            int jl = e & 31;
            int j  = c * CJ + jl;
            float xv = x[(mt * MT + m) * D_IN + j];
            float xc = fminf(fmaxf(xv, -1.0f), 1.0f);
            float t  = (xc + 1.0f) * 3.5f;           // h = 2/7
            int idx  = min((int)floorf(t), 6);
            float u  = t - (float)idx;
            float u2 = u * u, u3 = u2 * u;
            float c0 = 0.5f * (-u3 + 2.0f * u2 - u);
            float c1 = 0.5f * (3.0f * u3 - 5.0f * u2 + 2.0f);
            float c2 = 0.5f * (-3.0f * u3 + 4.0f * u2 + u);
            float c3 = 0.5f * (u3 - u2);
            int p0 = max(idx - 1, 0);
            int p3 = min(idx + 2, 7);
            float v[8];
            #pragma unroll
            for (int k = 0; k < 8; k++) {
                float s = 0.0f;
                s += (k == p0)      ? c0 : 0.0f;
                s += (k == idx)     ? c1 : 0.0f;
                s += (k == idx + 1) ? c2 : 0.0f;
                s += (k == p3)      ? c3 : 0.0f;
                v[k] = s;
            }
            int off = m * RSB + jl * 16;
            split_store(base, off, SEG + off, v);
        }
        // B: 1024 evals, 4 per thread
        #pragma unroll
        for (int e = tid; e < OB * CJ; e += 256) {
            int ol = e >> 5;
            int jl = e & 31;
            int oj = (oh * OB + ol) * D_IN + c * CJ + jl;
            float w = weights[oj];
            float4 cA = *(const float4*)&coeffs[oj * KNOTS];
            float4 cB = *(const float4*)&coeffs[oj * KNOTS + 4];
            float v[8] = { w * cA.x, w * cA.y, w * cA.z, w * cA.w,
                           w * cB.x, w * cB.y, w * cB.z, w * cB.w };
            int off = ol * RSB + jl * 16;
            split_store(base, 2 * SEG + off, 3 * SEG + off, v);
        }
    };

    // ---- fragment lane addresses ----
    // A x4 (m16 x k16): row = wm*16 + (L&7) + ((L>>3)&1)*8, col16 = L>>4
    // B x4 (n8  x k32): row = wn*8 + (L&7), col16 = L>>3  (4 k8-chunks)
    const uint32_t a_lane = (uint32_t)((wm * 16 + (lane & 7) + ((lane >> 3) & 1) * 8) * RSB
                                       + (lane >> 4) * 16);
    const uint32_t b_lane = (uint32_t)((wn * 8 + (lane & 7)) * RSB + (lane >> 3) * 16);

    float acc[4] = {0.0f, 0.0f, 0.0f, 0.0f};

    build(0, 0);
    __syncthreads();

    #pragma unroll 1
    for (int c = 0; c < NCH; c++) {
        if (c < NCH - 1) build(c + 1, (c + 1) & 1);  // overlaps with MMA below

        const uint32_t bb  = sb + (uint32_t)((c & 1) * BUF);
        const uint32_t aHI = bb + a_lane;
        const uint32_t aLO = bb + SEG + a_lane;
        const uint32_t bHI = bb + 2 * SEG + b_lane;
        const uint32_t bLO = bb + 3 * SEG + b_lane;

        #pragma unroll
        for (int i2 = 0; i2 < 8; i2++) {             // 8 x (2 kb = 32 k)
            uint32_t koff = (uint32_t)(i2 * 64);     // 32 k * 2B
            uint32_t a00, a01, a02, a03, a10, a11, a12, a13;  // A hi kb0, kb1
            uint32_t l00, l01, l02, l03, l10, l11, l12, l13;  // A lo kb0, kb1
            uint32_t bh0, bh1, bh2, bh3, bl0, bl1, bl2, bl3;  // B hi/lo k32
            LDSM4(a00, a01, a02, a03, aHI + koff);
            LDSM4(a10, a11, a12, a13, aHI + koff + 32);
            LDSM4(l00, l01, l02, l03, aLO + koff);
            LDSM4(l10, l11, l12, l13, aLO + koff + 32);
            LDSM4(bh0, bh1, bh2, bh3, bHI + koff);
            LDSM4(bl0, bl1, bl2, bl3, bLO + koff);

            // kb0: b frags (bh0,bh1)/(bl0,bl1); kb1: (bh2,bh3)/(bl2,bl3)
            MMA16816(acc, a00, a01, a02, a03, bh0, bh1);
            MMA16816(acc, a00, a01, a02, a03, bl0, bl1);
            MMA16816(acc, l00, l01, l02, l03, bh0, bh1);
            MMA16816(acc, a10, a11, a12, a13, bh2, bh3);
            MMA16816(acc, a10, a11, a12, a13, bl2, bl3);
            MMA16816(acc, l10, l11, l12, l13, bh2, bh3);
        }
        __syncthreads();
    }

    // ---- epilogue: acc + bias -> out (direct) ----
    {
        const int gid = lane >> 2;
        const int tig = lane & 3;
        const int row0 = mt * MT + wm * 16 + gid;
        const int col  = oh * OB + wn * 8 + tig * 2;
        float2 bv = *(const float2*)&bias[col];
        *(float2*)&out[(size_t)row0 * D_OUT + col] =
            make_float2(acc[0] + bv.x, acc[1] + bv.y);
        *(float2*)&out[(size_t)(row0 + 8) * D_OUT + col] =
            make_float2(acc[2] + bv.x, acc[3] + bv.y);
    }
}

extern "C" void kernel_launch(void* const* d_in, const int* in_sizes, int n_in,
                              void* d_out, int out_size) {
    const float* x       = (const float*)d_in[0];   // [1024,128]
    const float* coeffs  = (const float*)d_in[1];   // [128,128,8]
    const float* weights = (const float*)d_in[2];   // [128,128]
    const float* bias    = (const float*)d_in[3];   // [128]
    float* out = (float*)d_out;                     // [1024,128]

    cudaFuncSetAttribute(kan_mma_kernel,
                         cudaFuncAttributeMaxDynamicSharedMemorySize, SM_TOTAL);

    dim3 grid(N_ROWS / MT, D_OUT / OB);             // (32, 4)
    kan_mma_kernel<<<grid, 256, SM_TOTAL>>>(x, coeffs, weights, bias, out);
}